// round 5
// baseline (speedup 1.0000x reference)
#include <cuda_runtime.h>
#include <cstdint>
#include <cstddef>

#define N_TOK 8192
#define H_DIM 1024
#define V_DIM 32000

constexpr int BM = 128;
constexpr int BN = 256;
constexpr int BK = 64;            // int8 K elements per chunk = 64 bytes/row
constexpr int KT = H_DIM / BK;    // 16

// Scratch (no cudaMalloc allowed). Accessed ONLY from device code.
__device__ int8_t g_xq[(size_t)N_TOK * H_DIM];   // 8 MB
__device__ int8_t g_wq[(size_t)V_DIM * H_DIM];   // 32 MB
__device__ float  g_sx[N_TOK];
__device__ float  g_sw[V_DIM];
__device__ float  g_S[N_TOK];     // sum of exp(logits) per row
__device__ float  g_T[N_TOK];     // target logit per row
__device__ int    g_tgt[N_TOK];

// ---------------------------------------------------------------------------
// Per-row symmetric int8 quantization.  One warp per row (1024 floats).
// IS_X selects destination symbols in DEVICE code (no host symbol addresses!)
// ---------------------------------------------------------------------------
template <int IS_X>
__global__ void quant_rows(const float4* __restrict__ src) {
    const int row  = blockIdx.x * 8 + (threadIdx.x >> 5);
    const int lane = threadIdx.x & 31;
    const float4* s = src + (size_t)row * 256;
    float4 v[8];
    float m = 0.0f;
#pragma unroll
    for (int p = 0; p < 8; p++) {
        v[p] = s[lane + p * 32];
        m = fmaxf(m, fmaxf(fmaxf(fabsf(v[p].x), fabsf(v[p].y)),
                           fmaxf(fabsf(v[p].z), fabsf(v[p].w))));
    }
#pragma unroll
    for (int o = 16; o > 0; o >>= 1) m = fmaxf(m, __shfl_xor_sync(0xffffffffu, m, o));
    m = fmaxf(m, 1e-20f);
    const float inv = 127.0f / m;
    uint32_t* d = (IS_X ? (uint32_t*)g_xq : (uint32_t*)g_wq) + (size_t)row * 256;
#pragma unroll
    for (int p = 0; p < 8; p++) {
        int b0 = __float2int_rn(v[p].x * inv);
        int b1 = __float2int_rn(v[p].y * inv);
        int b2 = __float2int_rn(v[p].z * inv);
        int b3 = __float2int_rn(v[p].w * inv);
        d[lane + p * 32] = (uint32_t)(b0 & 0xff) | ((uint32_t)(b1 & 0xff) << 8)
                         | ((uint32_t)(b2 & 0xff) << 16) | ((uint32_t)b3 << 24);
    }
    if (lane == 0) {
        if (IS_X) { g_sx[row] = m * (1.0f / 127.0f); g_S[row] = 0.0f; }
        else      { g_sw[row] = m * (1.0f / 127.0f); }
    }
}

// Target dtype sniff (int64 vs int32), normalize to int32.
__global__ void prep_targets_kernel(const int* __restrict__ t) {
    __shared__ int nz;
    if (threadIdx.x == 0) nz = 0;
    __syncthreads();
    int local = 0;
    for (int i = threadIdx.x; i < 4096; i += 256) local |= t[2 * i + 1];
    if (local) atomicOr(&nz, 1);
    __syncthreads();
    bool is64 = (nz == 0);
    for (int i = threadIdx.x; i < N_TOK; i += 256)
        g_tgt[i] = is64 ? t[2 * i] : t[i];
}

// ---------------------------------------------------------------------------
// int8 GEMM (round-1 proven skeleton, bf16->s8 swap) + fused CE epilogue
// ---------------------------------------------------------------------------
__device__ __forceinline__ void cp16(uint32_t* dst, const void* src) {
    uint32_t d = (uint32_t)__cvta_generic_to_shared(dst);
    asm volatile("cp.async.cg.shared.global [%0], [%1], 16;\n" :: "r"(d), "l"(src));
}
__device__ __forceinline__ void imma(int* c, const uint32_t* a, uint32_t b0, uint32_t b1) {
    asm volatile("mma.sync.aligned.m16n8k32.row.col.s32.s8.s8.s32 "
                 "{%0,%1,%2,%3},{%4,%5,%6,%7},{%8,%9},{%0,%1,%2,%3};"
                 : "+r"(c[0]), "+r"(c[1]), "+r"(c[2]), "+r"(c[3])
                 : "r"(a[0]), "r"(a[1]), "r"(a[2]), "r"(a[3]), "r"(b0), "r"(b1));
}

// Swizzled tile layout (PROVEN in round 1): per 64-byte row, 4 chunks of 16B;
// chunk cc stored at position cc ^ ((row>>1)&3).
__device__ __forceinline__ void load_tile(uint32_t* As, uint32_t* Bs,
                                          int kt, int buf, int tid,
                                          int mBase, int vBase) {
    uint32_t* Ad = As + buf * 2048;
    const int8_t* xrow = g_xq + (size_t)mBase * H_DIM + kt * BK;
#pragma unroll
    for (int p = 0; p < 2; p++) {           // 128 rows * 4 chunks = 512
        int t = tid + p * 256;
        int row = t >> 2, cc = t & 3;
        int dw = row * 16 + ((cc ^ ((row >> 1) & 3)) << 2);
        cp16(Ad + dw, xrow + (size_t)row * H_DIM + cc * 16);
    }
    uint32_t* Bd = Bs + buf * 4096;
    const int8_t* wrow = g_wq + (size_t)vBase * H_DIM + kt * BK;
#pragma unroll
    for (int p = 0; p < 4; p++) {           // 256 rows * 4 chunks = 1024
        int t = tid + p * 256;
        int row = t >> 2, cc = t & 3;
        int dw = row * 16 + ((cc ^ ((row >> 1) & 3)) << 2);
        cp16(Bd + dw, wrow + (size_t)row * H_DIM + cc * 16);
    }
}

__global__ void __launch_bounds__(256, 1)
gemm_lce_i8(const float* __restrict__ bias) {
    extern __shared__ uint32_t smem[];
    uint32_t* As = smem;               // 2 bufs * 2048 words = 16 KB
    uint32_t* Bs = smem + 4096;        // 2 bufs * 4096 words = 32 KB
    float* sBias = (float*)(smem + 12288);   // 256 floats
    float* sSw   = (float*)(smem + 12544);   // 256 floats
    float* sSx   = (float*)(smem + 12800);   // 128 floats
    float* sRow  = (float*)(smem + 12928);   // 128 floats
    int*   sTgt  = (int*)  (smem + 13056);   // 128 ints

    const int tid  = threadIdx.x;
    const int lane = tid & 31;
    const int warp = tid >> 5;
    const int wm   = warp >> 2;   // 0..1  (m warps, 64 rows each)
    const int wn   = warp & 3;    // 0..3  (n warps, 64 cols each)
    const int g    = lane >> 2;   // groupID 0..7
    const int tig  = lane & 3;    // thread-in-group

    const int mBase = blockIdx.y * BM;
    const int vBase = blockIdx.x * BN;

    if (tid < 128) {
        sRow[tid] = 0.0f;
        sTgt[tid] = g_tgt[mBase + tid];
        sSx[tid]  = g_sx[mBase + tid];
    }
    sBias[tid] = bias[vBase + tid];
    sSw[tid]   = g_sw[vBase + tid];

    // Prefetch tile 0
    load_tile(As, Bs, 0, 0, tid, mBase, vBase);
    asm volatile("cp.async.commit_group;\n");

    int acc[4][8][4];
#pragma unroll
    for (int i = 0; i < 4; i++)
#pragma unroll
        for (int j = 0; j < 8; j++)
#pragma unroll
            for (int c = 0; c < 4; c++) acc[i][j][c] = 0;

    const int X = (g >> 1) & 3;             // swizzle xor, constant per thread
    const int raBase = (wm * 64 + g) * 16;  // A row base (words)
    const int rbBase = (wn * 64 + g) * 16;  // B row base (words)

    for (int kt = 0; kt < KT; kt++) {
        if (kt + 1 < KT) load_tile(As, Bs, kt + 1, (kt + 1) & 1, tid, mBase, vBase);
        asm volatile("cp.async.commit_group;\n");
        if (kt + 1 < KT) asm volatile("cp.async.wait_group 1;\n");
        else             asm volatile("cp.async.wait_group 0;\n");
        __syncthreads();

        const uint32_t* Ac = As + (kt & 1) * 2048;
        const uint32_t* Bc = Bs + (kt & 1) * 4096;

#pragma unroll
        for (int ks = 0; ks < 2; ks++) {    // each ks = k32 (two 16B chunks)
            const int off0 = (((ks * 2)     ^ X) << 2) + tig;  // k-lo word
            const int off1 = (((ks * 2 + 1) ^ X) << 2) + tig;  // k-hi word

            uint32_t a[4][4];
#pragma unroll
            for (int i = 0; i < 4; i++) {
                int base = raBase + i * 256;
                a[i][0] = Ac[base +       off0];
                a[i][1] = Ac[base + 128 + off0];
                a[i][2] = Ac[base +       off1];
                a[i][3] = Ac[base + 128 + off1];
            }
#pragma unroll
            for (int j = 0; j < 8; j++) {
                uint32_t b0 = Bc[rbBase + j * 128 + off0];
                uint32_t b1 = Bc[rbBase + j * 128 + off1];
#pragma unroll
                for (int i = 0; i < 4; i++) imma(acc[i][j], a[i], b0, b1);
            }
        }
        __syncthreads();
    }

    // ---------------- Epilogue: scales, bias, exp, row-sums, target --------
    float rs[4][2];
#pragma unroll
    for (int i = 0; i < 4; i++) { rs[i][0] = 0.0f; rs[i][1] = 0.0f; }

#pragma unroll
    for (int i = 0; i < 4; i++) {
#pragma unroll
        for (int h = 0; h < 2; h++) {
            const int lr = wm * 64 + i * 16 + h * 8 + g;
            const int tgt = sTgt[lr];
            const float sx = sSx[lr];
            float s = 0.0f;
#pragma unroll
            for (int j = 0; j < 8; j++) {
                const int cl = wn * 64 + j * 8 + tig * 2;
                float v0 = (float)acc[i][j][h * 2 + 0] * (sx * sSw[cl])     + sBias[cl];
                float v1 = (float)acc[i][j][h * 2 + 1] * (sx * sSw[cl + 1]) + sBias[cl + 1];
                const int gc = vBase + cl;
                if (tgt == gc)     g_T[mBase + lr] = v0;
                if (tgt == gc + 1) g_T[mBase + lr] = v1;
                s += __expf(v0) + __expf(v1);
            }
            rs[i][h] = s;
        }
    }
#pragma unroll
    for (int i = 0; i < 4; i++)
#pragma unroll
        for (int h = 0; h < 2; h++) {
            float s = rs[i][h];
            s += __shfl_xor_sync(0xffffffffu, s, 1);
            s += __shfl_xor_sync(0xffffffffu, s, 2);
            if (tig == 0)
                atomicAdd(&sRow[wm * 64 + i * 16 + h * 8 + g], s);
        }
    __syncthreads();
    if (tid < 128) atomicAdd(&g_S[mBase + tid], sRow[tid]);
}

// ---------------------------------------------------------------------------
// loss = sum(valid ? log(S) - T : 0) / max(#valid, 1)
// ---------------------------------------------------------------------------
__global__ void finalize_kernel(float* __restrict__ out) {
    __shared__ double red[256];
    __shared__ int  rcnt[256];
    double a = 0.0;
    int cnt = 0;
    for (int i = threadIdx.x; i < N_TOK; i += 256) {
        if (g_tgt[i] != -100) {
            a += (double)(logf(g_S[i]) - g_T[i]);
            cnt++;
        }
    }
    red[threadIdx.x] = a;
    rcnt[threadIdx.x] = cnt;
    __syncthreads();
    for (int s = 128; s > 0; s >>= 1) {
        if (threadIdx.x < s) {
            red[threadIdx.x]  += red[threadIdx.x + s];
            rcnt[threadIdx.x] += rcnt[threadIdx.x + s];
        }
        __syncthreads();
    }
    if (threadIdx.x == 0) {
        int c = rcnt[0] > 0 ? rcnt[0] : 1;
        out[0] = (float)(red[0] / (double)c);
    }
}

// ---------------------------------------------------------------------------
extern "C" void kernel_launch(void* const* d_in, const int* in_sizes, int n_in,
                              void* d_out, int out_size) {
    const float* x    = (const float*)d_in[0];
    const float* w    = (const float*)d_in[1];
    const float* bias = (const float*)d_in[2];
    const int*   tgt  = (const int*)d_in[3];
    float* out = (float*)d_out;

    // 13184 words = 52736 bytes of dynamic smem
    cudaFuncSetAttribute(gemm_lce_i8,
                         cudaFuncAttributeMaxDynamicSharedMemorySize, 52736);

    quant_rows<1><<<N_TOK / 8, 256>>>((const float4*)x);
    quant_rows<0><<<V_DIM / 8, 256>>>((const float4*)w);
    prep_targets_kernel<<<1, 256>>>(tgt);

    dim3 grid(V_DIM / BN, N_TOK / BM);   // (125, 64)
    gemm_lce_i8<<<grid, 256, 52736>>>(bias);

    finalize_kernel<<<1, 256>>>(out);
}

// round 6
// speedup vs baseline: 2.1096x; 2.1096x over previous
#include <cuda_runtime.h>
#include <cuda_bf16.h>
#include <cstdint>
#include <cstddef>

#define N_TOK 8192
#define H_DIM 1024
#define V_DIM 32000

constexpr int BM = 128;
constexpr int BN = 256;
constexpr int BK = 32;             // bf16 K per chunk = 64 bytes/row
constexpr int KT = H_DIM / BK;     // 32
constexpr int STAGES = 4;
constexpr int A_BYTES = BM * 64;               // 8192
constexpr int B_BYTES = BN * 64;               // 16384
constexpr int STAGE_BYTES = A_BYTES + B_BYTES; // 24576
constexpr int SMEM_BIAS = STAGES * STAGE_BYTES;     // 98304
constexpr int SMEM_TGT  = SMEM_BIAS + 1024;
constexpr int SMEM_ROW  = SMEM_TGT + 512;
constexpr int SMEM_TOTAL = SMEM_ROW + 512;          // 100352

// Scratch (no cudaMalloc). Referenced ONLY from device code.
__device__ __nv_bfloat16 g_xb[(size_t)N_TOK * H_DIM];   // 16 MB
__device__ __nv_bfloat16 g_wb[(size_t)V_DIM * H_DIM];   // 64 MB
__device__ float g_S[N_TOK];
__device__ float g_T[N_TOK];
__device__ int   g_tgt[N_TOK];

// ---------------------------------------------------------------------------
__device__ __forceinline__ uint32_t smem_u32(const void* p) {
    uint32_t a;
    asm("{ .reg .u64 t; cvta.to.shared.u64 t, %1; cvt.u32.u64 %0, t; }" : "=r"(a) : "l"(p));
    return a;
}
__device__ __forceinline__ void cp16(uint32_t daddr, const void* src) {
    asm volatile("cp.async.cg.shared.global [%0], [%1], 16;" :: "r"(daddr), "l"(src));
}
__device__ __forceinline__ void ldsm4(uint32_t* f, uint32_t addr) {
    asm volatile("ldmatrix.sync.aligned.m8n8.x4.shared.b16 {%0,%1,%2,%3}, [%4];"
                 : "=r"(f[0]), "=r"(f[1]), "=r"(f[2]), "=r"(f[3]) : "r"(addr));
}
__device__ __forceinline__ void hmma(float* c, const uint32_t* a, uint32_t b0, uint32_t b1) {
    asm volatile("mma.sync.aligned.m16n8k16.row.col.f32.bf16.bf16.f32 "
                 "{%0,%1,%2,%3},{%4,%5,%6,%7},{%8,%9},{%0,%1,%2,%3};"
                 : "+f"(c[0]), "+f"(c[1]), "+f"(c[2]), "+f"(c[3])
                 : "r"(a[0]), "r"(a[1]), "r"(a[2]), "r"(a[3]), "r"(b0), "r"(b1));
}

// ---------------------------------------------------------------------------
// f32 -> bf16 converts (+ zero exp-sum accumulator)  [proven round 1]
// ---------------------------------------------------------------------------
__global__ void convert_x_kernel(const float* __restrict__ x) {
    int i = blockIdx.x * blockDim.x + threadIdx.x;
    float4 v = reinterpret_cast<const float4*>(x)[i];
    uint32_t u0 = ((uint32_t)__bfloat16_as_ushort(__float2bfloat16(v.y)) << 16)
                | __bfloat16_as_ushort(__float2bfloat16(v.x));
    uint32_t u1 = ((uint32_t)__bfloat16_as_ushort(__float2bfloat16(v.w)) << 16)
                | __bfloat16_as_ushort(__float2bfloat16(v.z));
    reinterpret_cast<uint2*>(g_xb)[i] = make_uint2(u0, u1);
    if (i < N_TOK) g_S[i] = 0.0f;
}
__global__ void convert_w_kernel(const float* __restrict__ w) {
    int i = blockIdx.x * blockDim.x + threadIdx.x;
    float4 v = reinterpret_cast<const float4*>(w)[i];
    uint32_t u0 = ((uint32_t)__bfloat16_as_ushort(__float2bfloat16(v.y)) << 16)
                | __bfloat16_as_ushort(__float2bfloat16(v.x));
    uint32_t u1 = ((uint32_t)__bfloat16_as_ushort(__float2bfloat16(v.w)) << 16)
                | __bfloat16_as_ushort(__float2bfloat16(v.z));
    reinterpret_cast<uint2*>(g_wb)[i] = make_uint2(u0, u1);
}

// Target dtype sniff (int64 vs int32), normalize to int32.
__global__ void prep_targets_kernel(const int* __restrict__ t) {
    __shared__ int nz;
    if (threadIdx.x == 0) nz = 0;
    __syncthreads();
    int local = 0;
    for (int i = threadIdx.x; i < 4096; i += 256) local |= t[2 * i + 1];
    if (local) atomicOr(&nz, 1);
    __syncthreads();
    bool is64 = (nz == 0);
    for (int i = threadIdx.x; i < N_TOK; i += 256)
        g_tgt[i] = is64 ? t[2 * i] : t[i];
}

// ---------------------------------------------------------------------------
// Proven swizzle: 64B rows, 16B chunk cc of row r stored at chunk cc^((r>>1)&3).
// 512-thread tile loader: A = 512 chunks (1 pass), B = 1024 chunks (2 passes).
// ---------------------------------------------------------------------------
__device__ __forceinline__ void load_tile(uint32_t sbase, int slot, int kt,
                                          int mBase, int vBase, int tid) {
    const uint32_t aD = sbase + slot * STAGE_BYTES;
    {
        int row = tid >> 2, cc = tid & 3;
        cp16(aD + row * 64 + ((cc ^ ((row >> 1) & 3)) << 4),
             g_xb + (size_t)(mBase + row) * H_DIM + kt * BK + cc * 8);
    }
    const uint32_t bD = aD + A_BYTES;
#pragma unroll
    for (int p = 0; p < 2; p++) {
        int idx = tid + p * 512;
        int row = idx >> 2, cc = idx & 3;
        cp16(bD + row * 64 + ((cc ^ ((row >> 1) & 3)) << 4),
             g_wb + (size_t)(vBase + row) * H_DIM + kt * BK + cc * 8);
    }
}

__global__ void __launch_bounds__(512, 1)
gemm_lce_bf16(const float* __restrict__ bias) {
    extern __shared__ char smem[];
    const uint32_t sbase = smem_u32(smem);
    float* sBias = (float*)(smem + SMEM_BIAS);
    int*   sTgt  = (int*)  (smem + SMEM_TGT);
    float* sRow  = (float*)(smem + SMEM_ROW);

    const int tid  = threadIdx.x;
    const int lane = tid & 31;
    const int warp = tid >> 5;
    const int wm   = warp >> 3;    // 0..1  (64 rows)
    const int wn   = warp & 7;     // 0..7  (32 cols)
    const int g    = lane >> 2;
    const int tig  = lane & 3;

    const int mBase = blockIdx.y * BM;
    const int vBase = blockIdx.x * BN;

    // ldmatrix per-lane addressing (proven fragment mapping):
    // lanes 0-7: rows 0-7 khalf0 | 8-15: rows 8-15 khalf0 | 16-23: rows 0-7 khalf1 | 24-31: rows 8-15 khalf1
    const int rowoff = (lane & 7) + (((lane >> 3) & 1) << 3);
    const int khalf  = lane >> 4;
    const int X      = (rowoff >> 1) & 3;
    const uint32_t offk0 = (uint32_t)((khalf ^ X) << 4);
    const uint32_t offk1 = (uint32_t)(((2 + khalf) ^ X) << 4);
    const uint32_t aLane = (uint32_t)((wm * 64 + rowoff) * 64);
    const uint32_t bLane = (uint32_t)(A_BYTES + (wn * 32 + rowoff) * 64);

    if (tid < 128) { sRow[tid] = 0.0f; sTgt[tid] = g_tgt[mBase + tid]; }
    if (tid < 256) sBias[tid] = bias[vBase + tid];

    // Prologue: stages 0..2
#pragma unroll
    for (int p = 0; p < STAGES - 1; p++) {
        load_tile(sbase, p, p, mBase, vBase, tid);
        asm volatile("cp.async.commit_group;");
    }

    float acc[4][4][4];
#pragma unroll
    for (int i = 0; i < 4; i++)
#pragma unroll
        for (int j = 0; j < 4; j++)
#pragma unroll
            for (int c = 0; c < 4; c++) acc[i][j][c] = 0.0f;

    for (int kt = 0; kt < KT; kt++) {
        if (kt < KT - 2)       asm volatile("cp.async.wait_group 2;");
        else if (kt == KT - 2) asm volatile("cp.async.wait_group 1;");
        else                   asm volatile("cp.async.wait_group 0;");
        __syncthreads();
        if (kt + STAGES - 1 < KT) {
            load_tile(sbase, (kt + STAGES - 1) & 3, kt + STAGES - 1, mBase, vBase, tid);
            asm volatile("cp.async.commit_group;");
        }

        const uint32_t stg = sbase + (uint32_t)(kt & 3) * STAGE_BYTES;
        const uint32_t aA = stg + aLane;
        const uint32_t bA = stg + bLane;

#pragma unroll
        for (int ks = 0; ks < 2; ks++) {
            const uint32_t offk = ks ? offk1 : offk0;
            uint32_t a[4][4], b[2][4];
#pragma unroll
            for (int i = 0; i < 4; i++) ldsm4(a[i], aA + i * 1024 + offk);
#pragma unroll
            for (int ng = 0; ng < 2; ng++) ldsm4(b[ng], bA + ng * 1024 + offk);
#pragma unroll
            for (int j = 0; j < 4; j++) {
                const uint32_t b0 = b[j >> 1][j & 1];
                const uint32_t b1 = b[j >> 1][2 + (j & 1)];
#pragma unroll
                for (int i = 0; i < 4; i++) hmma(acc[i][j], a[i], b0, b1);
            }
        }
        __syncthreads();
    }

    // ---------------- Epilogue: bias, exp, row-sums, target ----------------
#pragma unroll
    for (int i = 0; i < 4; i++) {
#pragma unroll
        for (int h = 0; h < 2; h++) {
            const int lr  = wm * 64 + i * 16 + h * 8 + g;
            const int tgt = sTgt[lr];
            float s = 0.0f;
#pragma unroll
            for (int j = 0; j < 4; j++) {
                const int cl = wn * 32 + j * 8 + tig * 2;
                float v0 = acc[i][j][h * 2 + 0] + sBias[cl];
                float v1 = acc[i][j][h * 2 + 1] + sBias[cl + 1];
                const int gc = vBase + cl;
                if (tgt == gc)     g_T[mBase + lr] = v0;
                if (tgt == gc + 1) g_T[mBase + lr] = v1;
                s += __expf(v0) + __expf(v1);
            }
            s += __shfl_xor_sync(0xffffffffu, s, 1);
            s += __shfl_xor_sync(0xffffffffu, s, 2);
            if (tig == 0) atomicAdd(&sRow[lr], s);
        }
    }
    __syncthreads();
    if (tid < 128) atomicAdd(&g_S[mBase + tid], sRow[tid]);
}

// ---------------------------------------------------------------------------
// loss = sum(valid ? log(S) - T : 0) / max(#valid, 1)
// ---------------------------------------------------------------------------
__global__ void finalize_kernel(float* __restrict__ out) {
    __shared__ double red[256];
    __shared__ int  rcnt[256];
    double a = 0.0;
    int cnt = 0;
    for (int i = threadIdx.x; i < N_TOK; i += 256) {
        if (g_tgt[i] != -100) {
            a += (double)(logf(g_S[i]) - g_T[i]);
            cnt++;
        }
    }
    red[threadIdx.x] = a;
    rcnt[threadIdx.x] = cnt;
    __syncthreads();
    for (int s = 128; s > 0; s >>= 1) {
        if (threadIdx.x < s) {
            red[threadIdx.x]  += red[threadIdx.x + s];
            rcnt[threadIdx.x] += rcnt[threadIdx.x + s];
        }
        __syncthreads();
    }
    if (threadIdx.x == 0) {
        int c = rcnt[0] > 0 ? rcnt[0] : 1;
        out[0] = (float)(red[0] / (double)c);
    }
}

// ---------------------------------------------------------------------------
extern "C" void kernel_launch(void* const* d_in, const int* in_sizes, int n_in,
                              void* d_out, int out_size) {
    const float* x    = (const float*)d_in[0];
    const float* w    = (const float*)d_in[1];
    const float* bias = (const float*)d_in[2];
    const int*   tgt  = (const int*)d_in[3];
    float* out = (float*)d_out;

    cudaFuncSetAttribute(gemm_lce_bf16,
                         cudaFuncAttributeMaxDynamicSharedMemorySize, SMEM_TOTAL);

    convert_x_kernel<<<(N_TOK * H_DIM / 4) / 256, 256>>>(x);
    convert_w_kernel<<<(int)(((size_t)V_DIM * H_DIM / 4) / 256), 256>>>(w);
    prep_targets_kernel<<<1, 256>>>(tgt);

    dim3 grid(V_DIM / BN, N_TOK / BM);   // (125, 64)
    gemm_lce_bf16<<<grid, 512, SMEM_TOTAL>>>(bias);

    finalize_kernel<<<1, 256>>>(out);
}

// round 7
// speedup vs baseline: 2.3978x; 1.1367x over previous
#include <cuda_runtime.h>
#include <cuda_bf16.h>
#include <cstdint>
#include <cstddef>

#define N_TOK 8192
#define H_DIM 1024
#define V_DIM 32000

constexpr int BM = 128;
constexpr int BN = 128;
constexpr int BK = 64;             // two proven 32-k sub-blocks per stage
constexpr int KT = H_DIM / BK;     // 16
constexpr int STAGES = 3;
constexpr int SUB_BYTES = 128 * 64;            // 8192 (128 rows x 64B)
constexpr int A_BYTES = 2 * SUB_BYTES;         // 16384
constexpr int B_BYTES = 2 * SUB_BYTES;         // 16384
constexpr int STAGE_BYTES = A_BYTES + B_BYTES; // 32768
constexpr int SMEM_BIAS = STAGES * STAGE_BYTES;  // 98304
constexpr int SMEM_TGT  = SMEM_BIAS + 512;
constexpr int SMEM_ROW  = SMEM_TGT + 512;
constexpr int SMEM_TOTAL = SMEM_ROW + 512;       // 99840 (x2 CTAs = 195 KB)

// Scratch (no cudaMalloc). Referenced ONLY from device code.
__device__ __nv_bfloat16 g_xb[(size_t)N_TOK * H_DIM];   // 16 MB
__device__ __nv_bfloat16 g_wb[(size_t)V_DIM * H_DIM];   // 64 MB
__device__ float g_S[N_TOK];
__device__ float g_T[N_TOK];
__device__ int   g_tgt[N_TOK];

// ---------------------------------------------------------------------------
__device__ __forceinline__ uint32_t smem_u32(const void* p) {
    uint32_t a;
    asm("{ .reg .u64 t; cvta.to.shared.u64 t, %1; cvt.u32.u64 %0, t; }" : "=r"(a) : "l"(p));
    return a;
}
__device__ __forceinline__ void cp16(uint32_t daddr, const void* src) {
    asm volatile("cp.async.cg.shared.global [%0], [%1], 16;" :: "r"(daddr), "l"(src));
}
__device__ __forceinline__ void ldsm4(uint32_t* f, uint32_t addr) {
    asm volatile("ldmatrix.sync.aligned.m8n8.x4.shared.b16 {%0,%1,%2,%3}, [%4];"
                 : "=r"(f[0]), "=r"(f[1]), "=r"(f[2]), "=r"(f[3]) : "r"(addr));
}
__device__ __forceinline__ void hmma(float* c, const uint32_t* a, uint32_t b0, uint32_t b1) {
    asm volatile("mma.sync.aligned.m16n8k16.row.col.f32.bf16.bf16.f32 "
                 "{%0,%1,%2,%3},{%4,%5,%6,%7},{%8,%9},{%0,%1,%2,%3};"
                 : "+f"(c[0]), "+f"(c[1]), "+f"(c[2]), "+f"(c[3])
                 : "r"(a[0]), "r"(a[1]), "r"(a[2]), "r"(a[3]), "r"(b0), "r"(b1));
}

// ---------------------------------------------------------------------------
// f32 -> bf16 converts (+ zero exp-sum accumulator)  [proven]
// ---------------------------------------------------------------------------
__global__ void convert_x_kernel(const float* __restrict__ x) {
    int i = blockIdx.x * blockDim.x + threadIdx.x;
    float4 v = reinterpret_cast<const float4*>(x)[i];
    uint32_t u0 = ((uint32_t)__bfloat16_as_ushort(__float2bfloat16(v.y)) << 16)
                | __bfloat16_as_ushort(__float2bfloat16(v.x));
    uint32_t u1 = ((uint32_t)__bfloat16_as_ushort(__float2bfloat16(v.w)) << 16)
                | __bfloat16_as_ushort(__float2bfloat16(v.z));
    reinterpret_cast<uint2*>(g_xb)[i] = make_uint2(u0, u1);
    if (i < N_TOK) g_S[i] = 0.0f;
}
__global__ void convert_w_kernel(const float* __restrict__ w) {
    int i = blockIdx.x * blockDim.x + threadIdx.x;
    float4 v = reinterpret_cast<const float4*>(w)[i];
    uint32_t u0 = ((uint32_t)__bfloat16_as_ushort(__float2bfloat16(v.y)) << 16)
                | __bfloat16_as_ushort(__float2bfloat16(v.x));
    uint32_t u1 = ((uint32_t)__bfloat16_as_ushort(__float2bfloat16(v.w)) << 16)
                | __bfloat16_as_ushort(__float2bfloat16(v.z));
    reinterpret_cast<uint2*>(g_wb)[i] = make_uint2(u0, u1);
}

// Target dtype sniff (int64 vs int32), normalize to int32.
__global__ void prep_targets_kernel(const int* __restrict__ t) {
    __shared__ int nz;
    if (threadIdx.x == 0) nz = 0;
    __syncthreads();
    int local = 0;
    for (int i = threadIdx.x; i < 4096; i += 256) local |= t[2 * i + 1];
    if (local) atomicOr(&nz, 1);
    __syncthreads();
    bool is64 = (nz == 0);
    for (int i = threadIdx.x; i < N_TOK; i += 256)
        g_tgt[i] = is64 ? t[2 * i] : t[i];
}

// ---------------------------------------------------------------------------
// Stage loader: one k64 slice = two proven k32 sub-blocks (64B rows,
// 16B chunk cc of row r at cc ^ ((r>>1)&3)).  256 threads.
// A: 1024 cp16 (4/thread), B: 1024 cp16 (4/thread).
// ---------------------------------------------------------------------------
__device__ __forceinline__ void load_stage(uint32_t sbase, int slot, int kt,
                                           int mBase, int vBase, int tid) {
    const uint32_t stg = sbase + slot * STAGE_BYTES;
#pragma unroll
    for (int p = 0; p < 4; p++) {
        int idx = tid + p * 256;              // 0..1023
        int sub = idx >> 9, rem = idx & 511;
        int row = rem >> 2, cc = rem & 3;
        cp16(stg + sub * SUB_BYTES + row * 64 + ((cc ^ ((row >> 1) & 3)) << 4),
             g_xb + (size_t)(mBase + row) * H_DIM + kt * BK + sub * 32 + cc * 8);
    }
#pragma unroll
    for (int p = 0; p < 4; p++) {
        int idx = tid + p * 256;
        int sub = idx >> 9, rem = idx & 511;
        int row = rem >> 2, cc = rem & 3;
        cp16(stg + A_BYTES + sub * SUB_BYTES + row * 64 + ((cc ^ ((row >> 1) & 3)) << 4),
             g_wb + (size_t)(vBase + row) * H_DIM + kt * BK + sub * 32 + cc * 8);
    }
}

__global__ void __launch_bounds__(256, 2)
gemm_lce_bf16(const float* __restrict__ bias) {
    extern __shared__ char smem[];
    const uint32_t sbase = smem_u32(smem);
    float* sBias = (float*)(smem + SMEM_BIAS);
    int*   sTgt  = (int*)  (smem + SMEM_TGT);
    float* sRow  = (float*)(smem + SMEM_ROW);

    const int tid  = threadIdx.x;
    const int lane = tid & 31;
    const int warp = tid >> 5;
    const int wm   = warp >> 2;    // 0..1  (64 rows)
    const int wn   = warp & 3;     // 0..3  (32 cols)
    const int g    = lane >> 2;
    const int tig  = lane & 3;

    const int mBase = blockIdx.y * BM;
    const int vBase = blockIdx.x * BN;

    // Proven ldmatrix per-lane addressing
    const int rowoff = (lane & 7) + (((lane >> 3) & 1) << 3);
    const int khalf  = lane >> 4;
    const int X      = (rowoff >> 1) & 3;
    const uint32_t offk[2] = { (uint32_t)((khalf ^ X) << 4),
                               (uint32_t)(((2 + khalf) ^ X) << 4) };
    const uint32_t aLane = (uint32_t)((wm * 64 + rowoff) * 64);
    const uint32_t bLane = (uint32_t)(A_BYTES + (wn * 32 + rowoff) * 64);

    if (tid < 128) {
        sRow[tid]  = 0.0f;
        sTgt[tid]  = g_tgt[mBase + tid];
        sBias[tid] = bias[vBase + tid];
    }

    // Prologue: stages 0,1
#pragma unroll
    for (int p = 0; p < STAGES - 1; p++) {
        load_stage(sbase, p, p, mBase, vBase, tid);
        asm volatile("cp.async.commit_group;");
    }

    float acc[4][4][4];
#pragma unroll
    for (int i = 0; i < 4; i++)
#pragma unroll
        for (int j = 0; j < 4; j++)
#pragma unroll
            for (int c = 0; c < 4; c++) acc[i][j][c] = 0.0f;

    uint32_t af[2][4][4], bf[2][2][4];

    for (int kt = 0; kt < KT; kt++) {
        if (kt < KT - 1) asm volatile("cp.async.wait_group 1;");
        else             asm volatile("cp.async.wait_group 0;");
        __syncthreads();   // single barrier per chunk; also protects slot reuse
        if (kt + STAGES - 1 < KT) {
            load_stage(sbase, (kt + STAGES - 1) % STAGES, kt + STAGES - 1,
                       mBase, vBase, tid);
            asm volatile("cp.async.commit_group;");
        }

        const uint32_t stg = sbase + (uint32_t)(kt % STAGES) * STAGE_BYTES;

        // 4 micro-steps: (sub,ks) = (0,0)(0,1)(1,0)(1,1); double-buffered frags
        {
            const uint32_t aA = stg + aLane, bA = stg + bLane;
#pragma unroll
            for (int i = 0; i < 4; i++) ldsm4(af[0][i], aA + i * 1024 + offk[0]);
#pragma unroll
            for (int n = 0; n < 2; n++) ldsm4(bf[0][n], bA + n * 1024 + offk[0]);
        }
#pragma unroll
        for (int step = 0; step < 4; step++) {
            const int buf = step & 1;
            if (step < 3) {
                const int ns = (step + 1) >> 1, nk = (step + 1) & 1;
                const uint32_t aA = stg + ns * SUB_BYTES + aLane;
                const uint32_t bA = stg + ns * SUB_BYTES + bLane;
#pragma unroll
                for (int i = 0; i < 4; i++) ldsm4(af[buf ^ 1][i], aA + i * 1024 + offk[nk]);
#pragma unroll
                for (int n = 0; n < 2; n++) ldsm4(bf[buf ^ 1][n], bA + n * 1024 + offk[nk]);
            }
#pragma unroll
            for (int j = 0; j < 4; j++) {
                const uint32_t b0 = bf[buf][j >> 1][j & 1];
                const uint32_t b1 = bf[buf][j >> 1][2 + (j & 1)];
#pragma unroll
                for (int i = 0; i < 4; i++) hmma(acc[i][j], af[buf][i], b0, b1);
            }
        }
    }
    __syncthreads();

    // ---------------- Epilogue: bias, exp, row-sums, target ----------------
#pragma unroll
    for (int i = 0; i < 4; i++) {
#pragma unroll
        for (int h = 0; h < 2; h++) {
            const int lr  = wm * 64 + i * 16 + h * 8 + g;
            const int tgt = sTgt[lr];
            float s = 0.0f;
#pragma unroll
            for (int j = 0; j < 4; j++) {
                const int cl = wn * 32 + j * 8 + tig * 2;
                float v0 = acc[i][j][h * 2 + 0] + sBias[cl];
                float v1 = acc[i][j][h * 2 + 1] + sBias[cl + 1];
                const int gc = vBase + cl;
                if (tgt == gc)     g_T[mBase + lr] = v0;
                if (tgt == gc + 1) g_T[mBase + lr] = v1;
                s += __expf(v0) + __expf(v1);
            }
            s += __shfl_xor_sync(0xffffffffu, s, 1);
            s += __shfl_xor_sync(0xffffffffu, s, 2);
            if (tig == 0) atomicAdd(&sRow[lr], s);
        }
    }
    __syncthreads();
    if (tid < 128) atomicAdd(&g_S[mBase + tid], sRow[tid]);
}

// ---------------------------------------------------------------------------
// loss = sum(valid ? log(S) - T : 0) / max(#valid, 1)
// ---------------------------------------------------------------------------
__global__ void finalize_kernel(float* __restrict__ out) {
    __shared__ double red[256];
    __shared__ int  rcnt[256];
    double a = 0.0;
    int cnt = 0;
    for (int i = threadIdx.x; i < N_TOK; i += 256) {
        if (g_tgt[i] != -100) {
            a += (double)(logf(g_S[i]) - g_T[i]);
            cnt++;
        }
    }
    red[threadIdx.x] = a;
    rcnt[threadIdx.x] = cnt;
    __syncthreads();
    for (int s = 128; s > 0; s >>= 1) {
        if (threadIdx.x < s) {
            red[threadIdx.x]  += red[threadIdx.x + s];
            rcnt[threadIdx.x] += rcnt[threadIdx.x + s];
        }
        __syncthreads();
    }
    if (threadIdx.x == 0) {
        int c = rcnt[0] > 0 ? rcnt[0] : 1;
        out[0] = (float)(red[0] / (double)c);
    }
}

// ---------------------------------------------------------------------------
extern "C" void kernel_launch(void* const* d_in, const int* in_sizes, int n_in,
                              void* d_out, int out_size) {
    const float* x    = (const float*)d_in[0];
    const float* w    = (const float*)d_in[1];
    const float* bias = (const float*)d_in[2];
    const int*   tgt  = (const int*)d_in[3];
    float* out = (float*)d_out;

    cudaFuncSetAttribute(gemm_lce_bf16,
                         cudaFuncAttributeMaxDynamicSharedMemorySize, SMEM_TOTAL);

    convert_x_kernel<<<(N_TOK * H_DIM / 4) / 256, 256>>>(x);
    convert_w_kernel<<<(int)(((size_t)V_DIM * H_DIM / 4) / 256), 256>>>(w);
    prep_targets_kernel<<<1, 256>>>(tgt);

    dim3 grid(V_DIM / BN, N_TOK / BM);   // (250, 64) = 16000 CTAs
    gemm_lce_bf16<<<grid, 256, SMEM_TOTAL>>>(bias);

    finalize_kernel<<<1, 256>>>(out);
}